// round 9
// baseline (speedup 1.0000x reference)
#include <cuda_runtime.h>

#define HH 512
#define WW 512
#define BC 6
#define NPIX (HH * WW)

// tile geometry: 32 wide x 8 tall outputs, 128 threads (32x4), 2 rows/thread
#define TW 32
#define TH 8
#define HW 36     // TW + 4
#define HHALO 12  // TH + 4

// ---- static device scratch (no runtime allocation allowed) ----
// State recycling: counters start zero (CUDA zero-init) and every replay
// re-zeros them at a point ordered before their next use:
//   g_sum/g_sumsq : zeroed in k_sobel (before k_iter3's atomics)
//   g_gmax        : zeroed in k_norm  (after its last reader)
__device__ float g_gmag[BC * NPIX];
__device__ float g_xnA[BC * NPIX];
__device__ float g_ynA[BC * NPIX];
__device__ float g_xnB[BC * NPIX];
__device__ float g_ynB[BC * NPIX];
__device__ int    g_gmax[BC];
__device__ double g_sum[BC];
__device__ double g_sumsq[BC];

__device__ __forceinline__ int refl(int i, int n) {
    if (i < 0) i = -i;
    if (i >= n) i = 2 * (n - 1) - i;
    return i;
}

__device__ __forceinline__ float tanh_fast(float x) {
    float y;
    asm("tanh.approx.f32 %0, %1;" : "=f"(y) : "f"(x));
    return y;
}

// Branchless Cephes-style atan, max err ~2e-7 rad.
__device__ __forceinline__ float atan_fast(float x) {
    float ax = fabsf(x);
    bool big = ax > 2.414213562f;     // tan(3pi/8)
    bool mid = ax > 0.4142135624f;    // tan(pi/8)
    float num = big ? -1.0f : ax - 1.0f;
    float den = big ? ax : ax + 1.0f;
    float r = mid ? __fdividef(num, den) : ax;
    float base = big ? 1.57079632679f : (mid ? 0.78539816340f : 0.0f);
    float z = r * r;
    float p = fmaf(fmaf(fmaf(8.05374449538e-2f, z, -1.38776856032e-1f), z,
                        1.99777106478e-1f), z, -3.33329491539e-1f);
    float res = base + fmaf(p * z, r, r);
    return copysignf(res, x);
}

// -------------------- Sobel + rotate + gmag max --------------------
__global__ void k_sobel(const float* __restrict__ img) {
    int c = blockIdx.z;
    const float* p = img + c * NPIX;
    int x = blockIdx.x * 32 + threadIdx.x;
    int y = blockIdx.y * 8 + threadIdx.y;
    int tid = threadIdx.y * 32 + threadIdx.x;

    if (blockIdx.x == 0 && blockIdx.y == 0 && tid == 0) {
        g_sum[c] = 0.0;
        g_sumsq[c] = 0.0;
    }

    float a[3][3];
#pragma unroll
    for (int j = 0; j < 3; j++)
#pragma unroll
        for (int i = 0; i < 3; i++) {
            int yy = y + j - 1, xx = x + i - 1;
            a[j][i] = ((unsigned)yy < HH && (unsigned)xx < WW) ? p[yy * WW + xx] : 0.f;
        }
    float gx = (a[0][2] - a[0][0]) + 2.f * (a[1][2] - a[1][0]) + (a[2][2] - a[2][0]);
    float gy = (a[2][0] - a[0][0]) + 2.f * (a[2][1] - a[0][1]) + (a[2][2] - a[0][2]);
    // uniform input scale (imgmax) dropped: results are scale-invariant
    gx = fmaxf(gx, 1e-12f);
    gy = fmaxf(gy, 1e-12f);

    float gm = sqrtf(fmaf(gx, gx, gy * gy));
    float invg = 1.0f / gm;
    float x0 = gx * invg, y0 = gy * invg;
    const float ct = -4.3711388e-08f, st = 1.0f;  // fp32 cos/sin(pi/2)
    float xn = x0 * ct - y0 * st;
    float yn = y0 * ct + x0 * st;

    int o = c * NPIX + y * WW + x;
    g_gmag[o] = gm;
    g_xnA[o]  = xn;
    g_ynA[o]  = yn;

    __shared__ float sm[8];
    int lane = tid & 31, warp = tid >> 5;
    float m = gm;
#pragma unroll
    for (int off = 16; off; off >>= 1) m = fmaxf(m, __shfl_xor_sync(0xffffffffu, m, off));
    if (lane == 0) sm[warp] = m;
    __syncthreads();
    if (tid == 0) {
#pragma unroll
        for (int i = 1; i < 8; i++) m = fmaxf(m, sm[i]);
        atomicMax(&g_gmax[c], __float_as_int(m));
    }
}

// -------------------- shared tile loader for ETF iterations --------------------
__device__ __forceinline__ void load_tile(
    float4 (*sN)[HW], float (*sG)[HW],
    const float* __restrict__ gm, const float* __restrict__ xi,
    const float* __restrict__ yi, float ginv, int bx0, int by0, int tid) {
    bool interior = (bx0 >= 0) && (by0 >= 0) && (bx0 + HW <= WW) && (by0 + HHALO <= HH);
    if (interior) {
        for (int i = tid; i < HHALO * HW; i += 128) {
            int ly = i / HW, lx = i - ly * HW;
            int o = (by0 + ly) * WW + bx0 + lx;
            float gn = gm[o] * ginv;
            float xv = xi[o], yv = yi[o];
            sN[ly][lx] = make_float4(xv, yv, gn * xv, gn * yv);
            sG[ly][lx] = gn;
        }
    } else {
        for (int i = tid; i < HHALO * HW; i += 128) {
            int ly = i / HW, lx = i - ly * HW;
            int o = refl(by0 + ly, HH) * WW + refl(bx0 + lx, WW);
            float gn = gm[o] * ginv;
            float xv = xi[o], yv = yi[o];
            sN[ly][lx] = make_float4(xv, yv, gn * xv, gn * yv);
            sG[ly][lx] = gn;
        }
    }
}

// core 5x5 weighted accumulation for 2 consecutive rows per thread
__device__ __forceinline__ void etf_core(
    float4 (*sN)[HW], float (*sG)[HW], int tx, int row0,
    float* xr, float* yr) {
    float gc[2], xc[2], yc[2];
#pragma unroll
    for (int k = 0; k < 2; k++) {
        float4 v = sN[row0 + 2 + k][tx + 2];
        gc[k] = sG[row0 + 2 + k][tx + 2];
        xc[k] = v.x; yc[k] = v.y;
        xr[k] = 0.f; yr[k] = 0.f;
    }
#pragma unroll
    for (int r = 0; r < 6; r++) {
        float4 n5[5];
        float  g5[5];
#pragma unroll
        for (int dx = 0; dx < 5; dx++) {
            n5[dx] = sN[row0 + r][tx + dx];
            g5[dx] = sG[row0 + r][tx + dx];
        }
#pragma unroll
        for (int k = 0; k < 2; k++) {
            if (r >= k && r <= k + 4) {
#pragma unroll
                for (int dx = 0; dx < 5; dx++) {
                    float th  = tanh_fast(g5[dx] - gc[k]);
                    float dot = fmaf(xc[k], n5[dx].x, yc[k] * n5[dx].y);
                    float u   = fmaf(th, dot, dot);      // (1+tanh)*dot
                    xr[k] = fmaf(n5[dx].z, u, xr[k]);
                    yr[k] = fmaf(n5[dx].w, u, yr[k]);
                }
            }
        }
    }
}

// -------------------- ETF iterations 1 & 2 --------------------
// 2 rows/thread keeps live state small (natural ~42-45 regs) so ~11 blocks/SM
// fit, raising eligible warps per scheduler. (Forcing regs via launch_bounds
// spilled in round 6 — this restructures instead.)
__global__ void __launch_bounds__(128) k_iter(int sel) {
    __shared__ float4 sN[HHALO][HW];
    __shared__ float  sG[HHALO][HW];

    int c = blockIdx.z;
    const float* gm = g_gmag + c * NPIX;
    const float* xi = (sel ? g_xnB : g_xnA) + c * NPIX;
    const float* yi = (sel ? g_ynB : g_ynA) + c * NPIX;
    float* xo = (sel ? g_xnA : g_xnB) + c * NPIX;
    float* yo = (sel ? g_ynA : g_ynB) + c * NPIX;

    float ginv = 1.0f / __int_as_float(g_gmax[c]);
    int bx0 = blockIdx.x * TW - 2;
    int by0 = blockIdx.y * TH - 2;
    int tid = threadIdx.y * 32 + threadIdx.x;

    load_tile(sN, sG, gm, xi, yi, ginv, bx0, by0, tid);
    __syncthreads();

    int tx = threadIdx.x;
    int row0 = threadIdx.y * 2;
    int px = blockIdx.x * TW + tx;
    float xr[2], yr[2];
    etf_core(sN, sG, tx, row0, xr, yr);

#pragma unroll
    for (int k = 0; k < 2; k++) {
        float invm = rsqrtf(fmaf(xr[k], xr[k], yr[k] * yr[k]));
        int o = (blockIdx.y * TH + row0 + k) * WW + px;
        xo[o] = xr[k] * invm;
        yo[o] = yr[k] * invm;
    }
}

// -------------------- ETF iteration 3 fused with angle + stats --------------------
// Reduction: fp32 warp-level shuffles only (|a|<=90), then one fp64 no-return
// atomic per warp per counter. No smem stage, no trailing __syncthreads.
__global__ void __launch_bounds__(128) k_iter3(float* __restrict__ out) {
    __shared__ float4 sN[HHALO][HW];
    __shared__ float  sG[HHALO][HW];

    int c = blockIdx.z;
    const float* gm = g_gmag + c * NPIX;
    const float* xi = g_xnA + c * NPIX;   // iter1: A->B, iter2: B->A, iter3 reads A
    const float* yi = g_ynA + c * NPIX;

    float ginv = 1.0f / __int_as_float(g_gmax[c]);
    int bx0 = blockIdx.x * TW - 2;
    int by0 = blockIdx.y * TH - 2;
    int tid = threadIdx.y * 32 + threadIdx.x;

    load_tile(sN, sG, gm, xi, yi, ginv, bx0, by0, tid);
    __syncthreads();

    int tx = threadIdx.x;
    int row0 = threadIdx.y * 2;
    int px = blockIdx.x * TW + tx;
    float xr[2], yr[2];
    etf_core(sN, sG, tx, row0, xr, yr);

    float s = 0.f, s2 = 0.f;
#pragma unroll
    for (int k = 0; k < 2; k++) {
        // normalization cancels inside atan(-y/x); divide directly
        float t = __fdividef(-yr[k], xr[k]);
        float a = atan_fast(t) * 57.2957795131f;  // 180/pi
        int o = c * NPIX + (blockIdx.y * TH + row0 + k) * WW + px;
        out[o] = a;
        s += a;
        s2 = fmaf(a, a, s2);
    }

#pragma unroll
    for (int off = 16; off; off >>= 1) {
        s  += __shfl_xor_sync(0xffffffffu, s, off);
        s2 += __shfl_xor_sync(0xffffffffu, s2, off);
    }
    if ((tid & 31) == 0) {
        atomicAdd(&g_sum[c], (double)s);     // return unused -> REDG
        atomicAdd(&g_sumsq[c], (double)s2);
    }
}

// -------------------- normalize (float4) + recycle state --------------------
__global__ void k_norm(float* __restrict__ out) {
    __shared__ float smu, sinv;
    int c = blockIdx.y;
    if (threadIdx.x == 0) {
        double mean = g_sum[c] / (double)NPIX;
        double var  = g_sumsq[c] / (double)NPIX - mean * mean;
        smu  = (float)mean;
        sinv = (float)(1.0 / sqrt(var + 1e-5));
        if (blockIdx.x == 0) g_gmax[c] = 0;   // recycle for next replay
    }
    __syncthreads();
    float4* o4 = (float4*)(out + c * NPIX);
    int i = blockIdx.x * blockDim.x + threadIdx.x;
    float4 v = o4[i];
    float mu = smu, is = sinv;
    v.x = (v.x - mu) * is;
    v.y = (v.y - mu) * is;
    v.z = (v.z - mu) * is;
    v.w = (v.w - mu) * is;
    o4[i] = v;
}

extern "C" void kernel_launch(void* const* d_in, const int* in_sizes, int n_in,
                              void* d_out, int out_size) {
    const float* img = (const float*)d_in[0];
    float* out = (float*)d_out;

    k_sobel<<<dim3(WW / 32, HH / 8, BC), dim3(32, 8)>>>(img);
    k_iter<<<dim3(WW / TW, HH / TH, BC), dim3(32, 4)>>>(0);   // A -> B
    k_iter<<<dim3(WW / TW, HH / TH, BC), dim3(32, 4)>>>(1);   // B -> A
    k_iter3<<<dim3(WW / TW, HH / TH, BC), dim3(32, 4)>>>(out);// A -> out (+stats)
    k_norm<<<dim3(NPIX / 4 / 256, BC), 256>>>(out);
}

// round 10
// speedup vs baseline: 1.3461x; 1.3461x over previous
#include <cuda_runtime.h>

#define HH 512
#define WW 512
#define BC 6
#define NPIX (HH * WW)

// tile geometry: 32 wide x 16 tall outputs, 128 threads (32x4), 4 rows/thread
#define TW 32
#define TH 16
#define HW 36    // TW + 4
#define HHALO 20 // TH + 4

// ---- static device scratch (no runtime allocation allowed) ----
// State recycling: counters start zero (CUDA zero-init) and every replay
// re-zeros them at a point ordered before their next use:
//   g_sum/g_sumsq : zeroed in k_sobel (before k_iter3's atomics)
//   g_gmax        : zeroed in k_norm  (after its last reader)
__device__ float g_gmag[BC * NPIX];
__device__ float g_xnA[BC * NPIX];
__device__ float g_ynA[BC * NPIX];
__device__ float g_xnB[BC * NPIX];
__device__ float g_ynB[BC * NPIX];
__device__ int    g_gmax[BC];
__device__ double g_sum[BC];
__device__ double g_sumsq[BC];

__device__ __forceinline__ int refl(int i, int n) {
    if (i < 0) i = -i;
    if (i >= n) i = 2 * (n - 1) - i;
    return i;
}

__device__ __forceinline__ float tanh_fast(float x) {
    float y;
    asm("tanh.approx.f32 %0, %1;" : "=f"(y) : "f"(x));
    return y;
}

// Branchless Cephes-style atan, max err ~2e-7 rad.
__device__ __forceinline__ float atan_fast(float x) {
    float ax = fabsf(x);
    bool big = ax > 2.414213562f;     // tan(3pi/8)
    bool mid = ax > 0.4142135624f;    // tan(pi/8)
    float num = big ? -1.0f : ax - 1.0f;
    float den = big ? ax : ax + 1.0f;
    float r = mid ? __fdividef(num, den) : ax;
    float base = big ? 1.57079632679f : (mid ? 0.78539816340f : 0.0f);
    float z = r * r;
    float p = fmaf(fmaf(fmaf(8.05374449538e-2f, z, -1.38776856032e-1f), z,
                        1.99777106478e-1f), z, -3.33329491539e-1f);
    float res = base + fmaf(p * z, r, r);
    return copysignf(res, x);
}

// -------------------- Sobel + rotate + gmag max --------------------
// 4 vertical px per thread: 6x3 input window (18 LDG) for 4 outputs.
__global__ void __launch_bounds__(256) k_sobel(const float* __restrict__ img) {
    int c = blockIdx.z;
    const float* p = img + c * NPIX;
    int x  = blockIdx.x * 32 + threadIdx.x;
    int y0 = blockIdx.y * 32 + threadIdx.y * 4;
    int tid = threadIdx.y * 32 + threadIdx.x;

    if (blockIdx.x == 0 && blockIdx.y == 0 && tid == 0) {
        g_sum[c] = 0.0;
        g_sumsq[c] = 0.0;
    }

    // window: rows y0-1 .. y0+4 (6), cols x-1,x,x+1 (3); zero outside
    float a[6][3];
#pragma unroll
    for (int r = 0; r < 6; r++) {
#pragma unroll
        for (int i = 0; i < 3; i++) {
            int yy = y0 + r - 1, xx = x + i - 1;
            a[r][i] = ((unsigned)yy < HH && (unsigned)xx < WW) ? p[yy * WW + xx] : 0.f;
        }
    }

    float mloc = 0.f;
#pragma unroll
    for (int k = 0; k < 4; k++) {
        float gx = (a[k][2] - a[k][0]) + 2.f * (a[k + 1][2] - a[k + 1][0]) + (a[k + 2][2] - a[k + 2][0]);
        float gy = (a[k + 2][0] - a[k][0]) + 2.f * (a[k + 2][1] - a[k][1]) + (a[k + 2][2] - a[k][2]);
        // uniform input scale (imgmax) dropped: results are scale-invariant
        gx = fmaxf(gx, 1e-12f);
        gy = fmaxf(gy, 1e-12f);

        float gm = sqrtf(fmaf(gx, gx, gy * gy));
        float invg = 1.0f / gm;
        float x0 = gx * invg, y0v = gy * invg;
        const float ct = -4.3711388e-08f, st = 1.0f;  // fp32 cos/sin(pi/2)
        float xn = x0 * ct - y0v * st;
        float yn = y0v * ct + x0 * st;

        int o = c * NPIX + (y0 + k) * WW + x;
        g_gmag[o] = gm;
        g_xnA[o]  = xn;
        g_ynA[o]  = yn;
        mloc = fmaxf(mloc, gm);
    }

    __shared__ float sm[8];
    int lane = tid & 31, warp = tid >> 5;
    float m = mloc;
#pragma unroll
    for (int off = 16; off; off >>= 1) m = fmaxf(m, __shfl_xor_sync(0xffffffffu, m, off));
    if (lane == 0) sm[warp] = m;
    __syncthreads();
    if (tid == 0) {
#pragma unroll
        for (int i = 1; i < 8; i++) m = fmaxf(m, sm[i]);
        atomicMax(&g_gmax[c], __float_as_int(m));
    }
}

// -------------------- shared tile loader for ETF iterations --------------------
__device__ __forceinline__ void load_tile(
    float4 (*sN)[HW], float (*sG)[HW],
    const float* __restrict__ gm, const float* __restrict__ xi,
    const float* __restrict__ yi, float ginv, int bx0, int by0, int tid) {
    bool interior = (bx0 >= 0) && (by0 >= 0) && (bx0 + HW <= WW) && (by0 + HHALO <= HH);
    if (interior) {
        for (int i = tid; i < HHALO * HW; i += 128) {
            int ly = i / HW, lx = i - ly * HW;
            int o = (by0 + ly) * WW + bx0 + lx;
            float gn = gm[o] * ginv;
            float xv = xi[o], yv = yi[o];
            sN[ly][lx] = make_float4(xv, yv, gn * xv, gn * yv);
            sG[ly][lx] = gn;
        }
    } else {
        for (int i = tid; i < HHALO * HW; i += 128) {
            int ly = i / HW, lx = i - ly * HW;
            int o = refl(by0 + ly, HH) * WW + refl(bx0 + lx, WW);
            float gn = gm[o] * ginv;
            float xv = xi[o], yv = yi[o];
            sN[ly][lx] = make_float4(xv, yv, gn * xv, gn * yv);
            sG[ly][lx] = gn;
        }
    }
}

// core 5x5 weighted accumulation for 4 consecutive rows per thread
__device__ __forceinline__ void etf_core(
    float4 (*sN)[HW], float (*sG)[HW], int tx, int row0,
    float* xr, float* yr) {
    float gc[4], xc[4], yc[4];
#pragma unroll
    for (int k = 0; k < 4; k++) {
        float4 v = sN[row0 + 2 + k][tx + 2];
        gc[k] = sG[row0 + 2 + k][tx + 2];
        xc[k] = v.x; yc[k] = v.y;
        xr[k] = 0.f; yr[k] = 0.f;
    }
#pragma unroll
    for (int r = 0; r < 8; r++) {
        float4 n5[5];
        float  g5[5];
#pragma unroll
        for (int dx = 0; dx < 5; dx++) {
            n5[dx] = sN[row0 + r][tx + dx];
            g5[dx] = sG[row0 + r][tx + dx];
        }
#pragma unroll
        for (int k = 0; k < 4; k++) {
            if (r >= k && r <= k + 4) {
#pragma unroll
                for (int dx = 0; dx < 5; dx++) {
                    float th  = tanh_fast(g5[dx] - gc[k]);
                    float dot = fmaf(xc[k], n5[dx].x, yc[k] * n5[dx].y);
                    float u   = fmaf(th, dot, dot);      // (1+tanh)*dot
                    xr[k] = fmaf(n5[dx].z, u, xr[k]);
                    yr[k] = fmaf(n5[dx].w, u, yr[k]);
                }
            }
        }
    }
}

// -------------------- ETF iterations 1 & 2 --------------------
__global__ void __launch_bounds__(128) k_iter(int sel) {
    __shared__ float4 sN[HHALO][HW];
    __shared__ float  sG[HHALO][HW];

    int c = blockIdx.z;
    const float* gm = g_gmag + c * NPIX;
    const float* xi = (sel ? g_xnB : g_xnA) + c * NPIX;
    const float* yi = (sel ? g_ynB : g_ynA) + c * NPIX;
    float* xo = (sel ? g_xnA : g_xnB) + c * NPIX;
    float* yo = (sel ? g_ynA : g_ynB) + c * NPIX;

    float ginv = 1.0f / __int_as_float(g_gmax[c]);
    int bx0 = blockIdx.x * TW - 2;
    int by0 = blockIdx.y * TH - 2;
    int tid = threadIdx.y * 32 + threadIdx.x;

    load_tile(sN, sG, gm, xi, yi, ginv, bx0, by0, tid);
    __syncthreads();

    int tx = threadIdx.x;
    int row0 = threadIdx.y * 4;
    int px = blockIdx.x * TW + tx;
    float xr[4], yr[4];
    etf_core(sN, sG, tx, row0, xr, yr);

#pragma unroll
    for (int k = 0; k < 4; k++) {
        float invm = rsqrtf(fmaf(xr[k], xr[k], yr[k] * yr[k]));
        int o = (blockIdx.y * TH + row0 + k) * WW + px;
        xo[o] = xr[k] * invm;
        yo[o] = yr[k] * invm;
    }
}

// -------------------- ETF iteration 3 fused with angle + stats --------------------
// Stats reduction: fp32 warp shuffles -> smem block stage -> ONE fp64 atomic
// pair per block (512 per address vs 4096 with per-warp atomics; the L2 atomic
// ALU serializes per address, so this removes ~6-8us of epilogue tax).
__global__ void __launch_bounds__(128) k_iter3(float* __restrict__ out) {
    __shared__ float4 sN[HHALO][HW];
    __shared__ float  sG[HHALO][HW];
    __shared__ float  sS[4], sS2[4];

    int c = blockIdx.z;
    const float* gm = g_gmag + c * NPIX;
    const float* xi = g_xnA + c * NPIX;   // iter1: A->B, iter2: B->A, iter3 reads A
    const float* yi = g_ynA + c * NPIX;

    float ginv = 1.0f / __int_as_float(g_gmax[c]);
    int bx0 = blockIdx.x * TW - 2;
    int by0 = blockIdx.y * TH - 2;
    int tid = threadIdx.y * 32 + threadIdx.x;

    load_tile(sN, sG, gm, xi, yi, ginv, bx0, by0, tid);
    __syncthreads();

    int tx = threadIdx.x;
    int row0 = threadIdx.y * 4;
    int px = blockIdx.x * TW + tx;
    float xr[4], yr[4];
    etf_core(sN, sG, tx, row0, xr, yr);

    float s = 0.f, s2 = 0.f;
#pragma unroll
    for (int k = 0; k < 4; k++) {
        // normalization cancels inside atan(-y/x); divide directly
        float t = __fdividef(-yr[k], xr[k]);
        float a = atan_fast(t) * 57.2957795131f;  // 180/pi
        int o = c * NPIX + (blockIdx.y * TH + row0 + k) * WW + px;
        out[o] = a;
        s += a;
        s2 = fmaf(a, a, s2);
    }

#pragma unroll
    for (int off = 16; off; off >>= 1) {
        s  += __shfl_xor_sync(0xffffffffu, s, off);
        s2 += __shfl_xor_sync(0xffffffffu, s2, off);
    }
    int lane = tid & 31, warp = tid >> 5;
    if (lane == 0) { sS[warp] = s; sS2[warp] = s2; }
    __syncthreads();
    if (tid == 0) {
        float ts = sS[0] + sS[1] + sS[2] + sS[3];
        float ts2 = sS2[0] + sS2[1] + sS2[2] + sS2[3];
        atomicAdd(&g_sum[c], (double)ts);     // return unused -> REDG
        atomicAdd(&g_sumsq[c], (double)ts2);
    }
}

// -------------------- normalize (float4) + recycle state --------------------
__global__ void k_norm(float* __restrict__ out) {
    __shared__ float smu, sinv;
    int c = blockIdx.y;
    if (threadIdx.x == 0) {
        double mean = g_sum[c] / (double)NPIX;
        double var  = g_sumsq[c] / (double)NPIX - mean * mean;
        smu  = (float)mean;
        sinv = (float)(1.0 / sqrt(var + 1e-5));
        if (blockIdx.x == 0) g_gmax[c] = 0;   // recycle for next replay
    }
    __syncthreads();
    float4* o4 = (float4*)(out + c * NPIX);
    int i = blockIdx.x * blockDim.x + threadIdx.x;
    float4 v = o4[i];
    float mu = smu, is = sinv;
    v.x = (v.x - mu) * is;
    v.y = (v.y - mu) * is;
    v.z = (v.z - mu) * is;
    v.w = (v.w - mu) * is;
    o4[i] = v;
}

extern "C" void kernel_launch(void* const* d_in, const int* in_sizes, int n_in,
                              void* d_out, int out_size) {
    const float* img = (const float*)d_in[0];
    float* out = (float*)d_out;

    k_sobel<<<dim3(WW / 32, HH / 32, BC), dim3(32, 8)>>>(img);
    k_iter<<<dim3(WW / TW, HH / TH, BC), dim3(32, 4)>>>(0);   // A -> B
    k_iter<<<dim3(WW / TW, HH / TH, BC), dim3(32, 4)>>>(1);   // B -> A
    k_iter3<<<dim3(WW / TW, HH / TH, BC), dim3(32, 4)>>>(out);// A -> out (+stats)
    k_norm<<<dim3(NPIX / 4 / 256, BC), 256>>>(out);
}

// round 11
// speedup vs baseline: 1.4203x; 1.0552x over previous
#include <cuda_runtime.h>

#define HH 512
#define WW 512
#define BC 6
#define NPIX (HH * WW)

// tile geometry: 32 wide x 16 tall outputs, 128 threads (32x4), 4 rows/thread,
// each thread handles 2 channels packed in f32x2.
#define TW 32
#define TH 16
#define HW 36    // TW + 4
#define HHALO 20 // TH + 4

typedef unsigned long long ull;

// ---- static device scratch (no runtime allocation allowed) ----
// State recycling: counters start zero (CUDA zero-init) and every replay
// re-zeros them at a point ordered before their next use:
//   g_sum/g_sumsq : zeroed in k_sobel (before k_iter3's atomics)
//   g_gmax        : zeroed in k_norm  (after its last reader)
__device__ float g_gmag[BC * NPIX];
__device__ float g_xnA[BC * NPIX];
__device__ float g_ynA[BC * NPIX];
__device__ float g_xnB[BC * NPIX];
__device__ float g_ynB[BC * NPIX];
__device__ int    g_gmax[BC];
__device__ double g_sum[BC];
__device__ double g_sumsq[BC];

__device__ __forceinline__ int refl(int i, int n) {
    if (i < 0) i = -i;
    if (i >= n) i = 2 * (n - 1) - i;
    return i;
}

__device__ __forceinline__ float tanh_fast(float x) {
    float y;
    asm("tanh.approx.f32 %0, %1;" : "=f"(y) : "f"(x));
    return y;
}

// ---- packed f32x2 helpers (Blackwell) ----
__device__ __forceinline__ ull pk(float a, float b) {
    ull r; asm("mov.b64 %0, {%1, %2};" : "=l"(r) : "f"(a), "f"(b)); return r;
}
__device__ __forceinline__ void upk(ull v, float& a, float& b) {
    asm("mov.b64 {%0, %1}, %2;" : "=f"(a), "=f"(b) : "l"(v));
}
__device__ __forceinline__ ull mul2(ull a, ull b) {
    ull r; asm("mul.rn.f32x2 %0, %1, %2;" : "=l"(r) : "l"(a), "l"(b)); return r;
}
__device__ __forceinline__ ull fma2(ull a, ull b, ull c) {
    ull r; asm("fma.rn.f32x2 %0, %1, %2, %3;" : "=l"(r) : "l"(a), "l"(b), "l"(c)); return r;
}

// Branchless Cephes-style atan, max err ~2e-7 rad.
__device__ __forceinline__ float atan_fast(float x) {
    float ax = fabsf(x);
    bool big = ax > 2.414213562f;     // tan(3pi/8)
    bool mid = ax > 0.4142135624f;    // tan(pi/8)
    float num = big ? -1.0f : ax - 1.0f;
    float den = big ? ax : ax + 1.0f;
    float r = mid ? __fdividef(num, den) : ax;
    float base = big ? 1.57079632679f : (mid ? 0.78539816340f : 0.0f);
    float z = r * r;
    float p = fmaf(fmaf(fmaf(8.05374449538e-2f, z, -1.38776856032e-1f), z,
                        1.99777106478e-1f), z, -3.33329491539e-1f);
    float res = base + fmaf(p * z, r, r);
    return copysignf(res, x);
}

// -------------------- Sobel + rotate + gmag max --------------------
// 4 vertical px per thread: 6x3 input window (18 LDG) for 4 outputs.
__global__ void __launch_bounds__(256) k_sobel(const float* __restrict__ img) {
    int c = blockIdx.z;
    const float* p = img + c * NPIX;
    int x  = blockIdx.x * 32 + threadIdx.x;
    int y0 = blockIdx.y * 32 + threadIdx.y * 4;
    int tid = threadIdx.y * 32 + threadIdx.x;

    if (blockIdx.x == 0 && blockIdx.y == 0 && tid == 0) {
        g_sum[c] = 0.0;
        g_sumsq[c] = 0.0;
    }

    float a[6][3];
#pragma unroll
    for (int r = 0; r < 6; r++) {
#pragma unroll
        for (int i = 0; i < 3; i++) {
            int yy = y0 + r - 1, xx = x + i - 1;
            a[r][i] = ((unsigned)yy < HH && (unsigned)xx < WW) ? p[yy * WW + xx] : 0.f;
        }
    }

    float mloc = 0.f;
#pragma unroll
    for (int k = 0; k < 4; k++) {
        float gx = (a[k][2] - a[k][0]) + 2.f * (a[k + 1][2] - a[k + 1][0]) + (a[k + 2][2] - a[k + 2][0]);
        float gy = (a[k + 2][0] - a[k][0]) + 2.f * (a[k + 2][1] - a[k][1]) + (a[k + 2][2] - a[k][2]);
        // uniform input scale (imgmax) dropped: results are scale-invariant
        gx = fmaxf(gx, 1e-12f);
        gy = fmaxf(gy, 1e-12f);

        float gm = sqrtf(fmaf(gx, gx, gy * gy));
        float invg = 1.0f / gm;
        float x0 = gx * invg, y0v = gy * invg;
        const float ct = -4.3711388e-08f, st = 1.0f;  // fp32 cos/sin(pi/2)
        float xn = x0 * ct - y0v * st;
        float yn = y0v * ct + x0 * st;

        int o = c * NPIX + (y0 + k) * WW + x;
        g_gmag[o] = gm;
        g_xnA[o]  = xn;
        g_ynA[o]  = yn;
        mloc = fmaxf(mloc, gm);
    }

    __shared__ float sm[8];
    int lane = tid & 31, warp = tid >> 5;
    float m = mloc;
#pragma unroll
    for (int off = 16; off; off >>= 1) m = fmaxf(m, __shfl_xor_sync(0xffffffffu, m, off));
    if (lane == 0) sm[warp] = m;
    __syncthreads();
    if (tid == 0) {
#pragma unroll
        for (int i = 1; i < 8; i++) m = fmaxf(m, sm[i]);
        atomicMax(&g_gmax[c], __float_as_int(m));
    }
}

// -------------------- channel-paired shared tile loader --------------------
__device__ __forceinline__ void load_tile2(
    ull (*sXN)[HW], ull (*sYN)[HW], ull (*sGX)[HW], ull (*sGY)[HW],
    float2 (*sGN)[HW],
    const float* __restrict__ gm0, const float* __restrict__ gm1,
    const float* __restrict__ xi0, const float* __restrict__ xi1,
    const float* __restrict__ yi0, const float* __restrict__ yi1,
    float ginv0, float ginv1, int bx0, int by0, int tid) {
    bool interior = (bx0 >= 0) && (by0 >= 0) && (bx0 + HW <= WW) && (by0 + HHALO <= HH);
    for (int i = tid; i < HHALO * HW; i += 128) {
        int ly = i / HW, lx = i - ly * HW;
        int o;
        if (interior) {
            o = (by0 + ly) * WW + bx0 + lx;
        } else {
            o = refl(by0 + ly, HH) * WW + refl(bx0 + lx, WW);
        }
        float g0 = gm0[o] * ginv0, g1 = gm1[o] * ginv1;
        float a0 = xi0[o], a1 = xi1[o];
        float b0 = yi0[o], b1 = yi1[o];
        sXN[ly][lx] = pk(a0, a1);
        sYN[ly][lx] = pk(b0, b1);
        sGX[ly][lx] = pk(g0 * a0, g1 * a1);
        sGY[ly][lx] = pk(g0 * b0, g1 * b1);
        sGN[ly][lx] = make_float2(g0, g1);
    }
}

// core 5x5 weighted accumulation: 4 consecutive rows x 2 channels per thread.
// Every fma-pipe op is f32x2 (2 channels per instruction); only tanh is scalar.
__device__ __forceinline__ void etf_core2(
    const ull (*sXN)[HW], const ull (*sYN)[HW], const ull (*sGX)[HW],
    const ull (*sGY)[HW], const float2 (*sGN)[HW],
    int tx, int row0, ull* xr2, ull* yr2) {
    ull xc2[4], yc2[4];
    float gc0[4], gc1[4];
#pragma unroll
    for (int k = 0; k < 4; k++) {
        xc2[k] = sXN[row0 + 2 + k][tx + 2];
        yc2[k] = sYN[row0 + 2 + k][tx + 2];
        float2 g = sGN[row0 + 2 + k][tx + 2];
        gc0[k] = g.x; gc1[k] = g.y;
        xr2[k] = 0ull; yr2[k] = 0ull;   // bits zero == (0.f, 0.f)
    }
#pragma unroll
    for (int r = 0; r < 8; r++) {
#pragma unroll
        for (int dx = 0; dx < 5; dx++) {
            ull xn2 = sXN[row0 + r][tx + dx];
            ull yn2 = sYN[row0 + r][tx + dx];
            ull gx2 = sGX[row0 + r][tx + dx];
            ull gy2 = sGY[row0 + r][tx + dx];
            float2 gn = sGN[row0 + r][tx + dx];
#pragma unroll
            for (int k = 0; k < 4; k++) {
                if (r >= k && r <= k + 4) {   // static predicate, fully unrolled
                    float th0 = tanh_fast(gn.x - gc0[k]);
                    float th1 = tanh_fast(gn.y - gc1[k]);
                    ull th2 = pk(th0, th1);
                    ull dot2 = fma2(xc2[k], xn2, mul2(yc2[k], yn2));
                    ull u2 = fma2(th2, dot2, dot2);      // (1+tanh)*dot
                    xr2[k] = fma2(gx2, u2, xr2[k]);
                    yr2[k] = fma2(gy2, u2, yr2[k]);
                }
            }
        }
    }
}

// -------------------- ETF iterations 1 & 2 (2 channels per block) ------------
__global__ void __launch_bounds__(128) k_iter(int sel) {
    __shared__ ull    sXN[HHALO][HW];
    __shared__ ull    sYN[HHALO][HW];
    __shared__ ull    sGX[HHALO][HW];
    __shared__ ull    sGY[HHALO][HW];
    __shared__ float2 sGN[HHALO][HW];

    int c0 = blockIdx.z * 2, c1 = c0 + 1;
    const float* xiB = sel ? g_xnB : g_xnA;
    const float* yiB = sel ? g_ynB : g_ynA;
    float* xoB = sel ? g_xnA : g_xnB;
    float* yoB = sel ? g_ynA : g_ynB;

    float ginv0 = 1.0f / __int_as_float(g_gmax[c0]);
    float ginv1 = 1.0f / __int_as_float(g_gmax[c1]);
    int bx0 = blockIdx.x * TW - 2;
    int by0 = blockIdx.y * TH - 2;
    int tid = threadIdx.y * 32 + threadIdx.x;

    load_tile2(sXN, sYN, sGX, sGY, sGN,
               g_gmag + c0 * NPIX, g_gmag + c1 * NPIX,
               xiB + c0 * NPIX, xiB + c1 * NPIX,
               yiB + c0 * NPIX, yiB + c1 * NPIX,
               ginv0, ginv1, bx0, by0, tid);
    __syncthreads();

    int tx = threadIdx.x;
    int row0 = threadIdx.y * 4;
    int px = blockIdx.x * TW + tx;
    ull xr2[4], yr2[4];
    etf_core2(sXN, sYN, sGX, sGY, sGN, tx, row0, xr2, yr2);

#pragma unroll
    for (int k = 0; k < 4; k++) {
        float x0, x1, y0v, y1;
        upk(xr2[k], x0, x1);
        upk(yr2[k], y0v, y1);
        float i0 = rsqrtf(fmaf(x0, x0, y0v * y0v));
        float i1 = rsqrtf(fmaf(x1, x1, y1 * y1));
        int o = (blockIdx.y * TH + row0 + k) * WW + px;
        xoB[c0 * NPIX + o] = x0 * i0;
        yoB[c0 * NPIX + o] = y0v * i0;
        xoB[c1 * NPIX + o] = x1 * i1;
        yoB[c1 * NPIX + o] = y1 * i1;
    }
}

// -------------------- ETF iteration 3 fused with angle + stats ---------------
// Per-channel stats: fp32 warp shuffles -> smem block stage -> ONE fp64 atomic
// pair per channel per block.
__global__ void __launch_bounds__(128) k_iter3(float* __restrict__ out) {
    __shared__ ull    sXN[HHALO][HW];
    __shared__ ull    sYN[HHALO][HW];
    __shared__ ull    sGX[HHALO][HW];
    __shared__ ull    sGY[HHALO][HW];
    __shared__ float2 sGN[HHALO][HW];
    __shared__ float  sS[4][4];   // [warp][s0,s20,s1,s21]

    int c0 = blockIdx.z * 2, c1 = c0 + 1;
    float ginv0 = 1.0f / __int_as_float(g_gmax[c0]);
    float ginv1 = 1.0f / __int_as_float(g_gmax[c1]);
    int bx0 = blockIdx.x * TW - 2;
    int by0 = blockIdx.y * TH - 2;
    int tid = threadIdx.y * 32 + threadIdx.x;

    load_tile2(sXN, sYN, sGX, sGY, sGN,
               g_gmag + c0 * NPIX, g_gmag + c1 * NPIX,
               g_xnA + c0 * NPIX, g_xnA + c1 * NPIX,   // iter3 reads A
               g_ynA + c0 * NPIX, g_ynA + c1 * NPIX,
               ginv0, ginv1, bx0, by0, tid);
    __syncthreads();

    int tx = threadIdx.x;
    int row0 = threadIdx.y * 4;
    int px = blockIdx.x * TW + tx;
    ull xr2[4], yr2[4];
    etf_core2(sXN, sYN, sGX, sGY, sGN, tx, row0, xr2, yr2);

    float s0 = 0.f, s20 = 0.f, s1 = 0.f, s21 = 0.f;
#pragma unroll
    for (int k = 0; k < 4; k++) {
        float x0, x1, y0v, y1;
        upk(xr2[k], x0, x1);
        upk(yr2[k], y0v, y1);
        int o = (blockIdx.y * TH + row0 + k) * WW + px;
        // normalization cancels inside atan(-y/x); divide directly
        float a0 = atan_fast(__fdividef(-y0v, x0)) * 57.2957795131f;
        float a1 = atan_fast(__fdividef(-y1, x1)) * 57.2957795131f;
        out[c0 * NPIX + o] = a0;
        out[c1 * NPIX + o] = a1;
        s0 += a0; s20 = fmaf(a0, a0, s20);
        s1 += a1; s21 = fmaf(a1, a1, s21);
    }

#pragma unroll
    for (int off = 16; off; off >>= 1) {
        s0  += __shfl_xor_sync(0xffffffffu, s0, off);
        s20 += __shfl_xor_sync(0xffffffffu, s20, off);
        s1  += __shfl_xor_sync(0xffffffffu, s1, off);
        s21 += __shfl_xor_sync(0xffffffffu, s21, off);
    }
    int lane = tid & 31, warp = tid >> 5;
    if (lane == 0) {
        sS[warp][0] = s0; sS[warp][1] = s20;
        sS[warp][2] = s1; sS[warp][3] = s21;
    }
    __syncthreads();
    if (tid == 0) {
        float t0 = sS[0][0] + sS[1][0] + sS[2][0] + sS[3][0];
        float t1 = sS[0][1] + sS[1][1] + sS[2][1] + sS[3][1];
        float t2 = sS[0][2] + sS[1][2] + sS[2][2] + sS[3][2];
        float t3 = sS[0][3] + sS[1][3] + sS[2][3] + sS[3][3];
        atomicAdd(&g_sum[c0], (double)t0);     // return unused -> REDG
        atomicAdd(&g_sumsq[c0], (double)t1);
        atomicAdd(&g_sum[c1], (double)t2);
        atomicAdd(&g_sumsq[c1], (double)t3);
    }
}

// -------------------- normalize (float4) + recycle state --------------------
__global__ void k_norm(float* __restrict__ out) {
    __shared__ float smu, sinv;
    int c = blockIdx.y;
    if (threadIdx.x == 0) {
        double mean = g_sum[c] / (double)NPIX;
        double var  = g_sumsq[c] / (double)NPIX - mean * mean;
        smu  = (float)mean;
        sinv = (float)(1.0 / sqrt(var + 1e-5));
        if (blockIdx.x == 0) g_gmax[c] = 0;   // recycle for next replay
    }
    __syncthreads();
    float4* o4 = (float4*)(out + c * NPIX);
    int i = blockIdx.x * blockDim.x + threadIdx.x;
    float4 v = o4[i];
    float mu = smu, is = sinv;
    v.x = (v.x - mu) * is;
    v.y = (v.y - mu) * is;
    v.z = (v.z - mu) * is;
    v.w = (v.w - mu) * is;
    o4[i] = v;
}

extern "C" void kernel_launch(void* const* d_in, const int* in_sizes, int n_in,
                              void* d_out, int out_size) {
    const float* img = (const float*)d_in[0];
    float* out = (float*)d_out;

    k_sobel<<<dim3(WW / 32, HH / 32, BC), dim3(32, 8)>>>(img);
    k_iter<<<dim3(WW / TW, HH / TH, BC / 2), dim3(32, 4)>>>(0);   // A -> B
    k_iter<<<dim3(WW / TW, HH / TH, BC / 2), dim3(32, 4)>>>(1);   // B -> A
    k_iter3<<<dim3(WW / TW, HH / TH, BC / 2), dim3(32, 4)>>>(out);// A -> out (+stats)
    k_norm<<<dim3(NPIX / 4 / 256, BC), 256>>>(out);
}

// round 12
// speedup vs baseline: 1.4800x; 1.0420x over previous
#include <cuda_runtime.h>

#define HH 512
#define WW 512
#define BC 6
#define NPIX (HH * WW)

// tile geometry: 32 wide x 16 tall outputs, 128 threads (32x4), 4 rows/thread,
// each thread handles 2 channels packed in f32x2.
#define TW 32
#define TH 16
#define HW 36    // TW + 4
#define HHALO 20 // TH + 4

typedef unsigned long long ull;

// ---- static device scratch (no runtime allocation allowed) ----
// State recycling: counters start zero (CUDA zero-init) and every replay
// re-zeros them at a point ordered before their next use:
//   g_sum/g_sumsq : zeroed in k_sobel (before k_iter3's atomics)
//   g_gmax        : zeroed in k_norm  (after its last reader)
__device__ float g_gmag[BC * NPIX];
__device__ float g_xnA[BC * NPIX];
__device__ float g_ynA[BC * NPIX];
__device__ float g_xnB[BC * NPIX];
__device__ float g_ynB[BC * NPIX];
__device__ int    g_gmax[BC];
__device__ double g_sum[BC];
__device__ double g_sumsq[BC];

__device__ __forceinline__ int refl(int i, int n) {
    if (i < 0) i = -i;
    if (i >= n) i = 2 * (n - 1) - i;
    return i;
}

__device__ __forceinline__ float tanh_fast(float x) {
    float y;
    asm("tanh.approx.f32 %0, %1;" : "=f"(y) : "f"(x));
    return y;
}

// ---- packed f32x2 helpers (Blackwell) ----
__device__ __forceinline__ ull pk(float a, float b) {
    ull r; asm("mov.b64 %0, {%1, %2};" : "=l"(r) : "f"(a), "f"(b)); return r;
}
__device__ __forceinline__ void upk(ull v, float& a, float& b) {
    asm("mov.b64 {%0, %1}, %2;" : "=f"(a), "=f"(b) : "l"(v));
}
__device__ __forceinline__ ull mul2(ull a, ull b) {
    ull r; asm("mul.rn.f32x2 %0, %1, %2;" : "=l"(r) : "l"(a), "l"(b)); return r;
}
__device__ __forceinline__ ull fma2(ull a, ull b, ull c) {
    ull r; asm("fma.rn.f32x2 %0, %1, %2, %3;" : "=l"(r) : "l"(a), "l"(b), "l"(c)); return r;
}

// Branchless Cephes-style atan, max err ~2e-7 rad.
__device__ __forceinline__ float atan_fast(float x) {
    float ax = fabsf(x);
    bool big = ax > 2.414213562f;     // tan(3pi/8)
    bool mid = ax > 0.4142135624f;    // tan(pi/8)
    float num = big ? -1.0f : ax - 1.0f;
    float den = big ? ax : ax + 1.0f;
    float r = mid ? __fdividef(num, den) : ax;
    float base = big ? 1.57079632679f : (mid ? 0.78539816340f : 0.0f);
    float z = r * r;
    float p = fmaf(fmaf(fmaf(8.05374449538e-2f, z, -1.38776856032e-1f), z,
                        1.99777106478e-1f), z, -3.33329491539e-1f);
    float res = base + fmaf(p * z, r, r);
    return copysignf(res, x);
}

// -------------------- Sobel + rotate + gmag max --------------------
// 4 vertical px per thread: 6x3 input window (18 LDG) for 4 outputs.
__global__ void __launch_bounds__(256) k_sobel(const float* __restrict__ img) {
    int c = blockIdx.z;
    const float* p = img + c * NPIX;
    int x  = blockIdx.x * 32 + threadIdx.x;
    int y0 = blockIdx.y * 32 + threadIdx.y * 4;
    int tid = threadIdx.y * 32 + threadIdx.x;

    if (blockIdx.x == 0 && blockIdx.y == 0 && tid == 0) {
        g_sum[c] = 0.0;
        g_sumsq[c] = 0.0;
    }

    float a[6][3];
#pragma unroll
    for (int r = 0; r < 6; r++) {
#pragma unroll
        for (int i = 0; i < 3; i++) {
            int yy = y0 + r - 1, xx = x + i - 1;
            a[r][i] = ((unsigned)yy < HH && (unsigned)xx < WW) ? p[yy * WW + xx] : 0.f;
        }
    }

    float mloc = 0.f;
#pragma unroll
    for (int k = 0; k < 4; k++) {
        float gx = (a[k][2] - a[k][0]) + 2.f * (a[k + 1][2] - a[k + 1][0]) + (a[k + 2][2] - a[k + 2][0]);
        float gy = (a[k + 2][0] - a[k][0]) + 2.f * (a[k + 2][1] - a[k][1]) + (a[k + 2][2] - a[k][2]);
        // uniform input scale (imgmax) dropped: results are scale-invariant
        gx = fmaxf(gx, 1e-12f);
        gy = fmaxf(gy, 1e-12f);

        float gm = sqrtf(fmaf(gx, gx, gy * gy));
        float invg = 1.0f / gm;
        float x0 = gx * invg, y0v = gy * invg;
        const float ct = -4.3711388e-08f, st = 1.0f;  // fp32 cos/sin(pi/2)
        float xn = x0 * ct - y0v * st;
        float yn = y0v * ct + x0 * st;

        int o = c * NPIX + (y0 + k) * WW + x;
        g_gmag[o] = gm;
        g_xnA[o]  = xn;
        g_ynA[o]  = yn;
        mloc = fmaxf(mloc, gm);
    }

    __shared__ float sm[8];
    int lane = tid & 31, warp = tid >> 5;
    float m = mloc;
#pragma unroll
    for (int off = 16; off; off >>= 1) m = fmaxf(m, __shfl_xor_sync(0xffffffffu, m, off));
    if (lane == 0) sm[warp] = m;
    __syncthreads();
    if (tid == 0) {
#pragma unroll
        for (int i = 1; i < 8; i++) m = fmaxf(m, sm[i]);
        atomicMax(&g_gmax[c], __float_as_int(m));
    }
}

// -------------------- channel-paired shared tile loader (3 arrays) ----------
__device__ __forceinline__ void load_tile2(
    ull (*sXN)[HW], ull (*sYN)[HW], ull (*sGN)[HW],
    const float* __restrict__ gm0, const float* __restrict__ gm1,
    const float* __restrict__ xi0, const float* __restrict__ xi1,
    const float* __restrict__ yi0, const float* __restrict__ yi1,
    float ginv0, float ginv1, int bx0, int by0, int tid) {
    bool interior = (bx0 >= 0) && (by0 >= 0) && (bx0 + HW <= WW) && (by0 + HHALO <= HH);
    for (int i = tid; i < HHALO * HW; i += 128) {
        int ly = i / HW, lx = i - ly * HW;
        int o;
        if (interior) {
            o = (by0 + ly) * WW + bx0 + lx;
        } else {
            o = refl(by0 + ly, HH) * WW + refl(bx0 + lx, WW);
        }
        sXN[ly][lx] = pk(xi0[o], xi1[o]);
        sYN[ly][lx] = pk(yi0[o], yi1[o]);
        sGN[ly][lx] = pk(gm0[o] * ginv0, gm1[o] * ginv1);
    }
}

// core 5x5 weighted accumulation: 4 consecutive rows x 2 channels per thread.
// 3 LDS.64 per neighbor position; all fp math on the fma pipe is f32x2.
__device__ __forceinline__ void etf_core2(
    const ull (*sXN)[HW], const ull (*sYN)[HW], const ull (*sGN)[HW],
    int tx, int row0, ull* xr2, ull* yr2) {
    ull xc2[4], yc2[4];
    float gc0[4], gc1[4];
#pragma unroll
    for (int k = 0; k < 4; k++) {
        xc2[k] = sXN[row0 + 2 + k][tx + 2];
        yc2[k] = sYN[row0 + 2 + k][tx + 2];
        float g0, g1;
        upk(sGN[row0 + 2 + k][tx + 2], g0, g1);
        gc0[k] = g0; gc1[k] = g1;
        xr2[k] = 0ull; yr2[k] = 0ull;   // bits zero == (0.f, 0.f)
    }
#pragma unroll
    for (int r = 0; r < 8; r++) {
#pragma unroll
        for (int dx = 0; dx < 5; dx++) {
            ull xn2 = sXN[row0 + r][tx + dx];
            ull yn2 = sYN[row0 + r][tx + dx];
            ull gn2 = sGN[row0 + r][tx + dx];
            float g0, g1;
            upk(gn2, g0, g1);
#pragma unroll
            for (int k = 0; k < 4; k++) {
                if (r >= k && r <= k + 4) {   // static predicate, fully unrolled
                    float th0 = tanh_fast(g0 - gc0[k]);
                    float th1 = tanh_fast(g1 - gc1[k]);
                    ull th2 = pk(th0, th1);
                    ull dot2 = fma2(xc2[k], xn2, mul2(yc2[k], yn2));
                    ull u2 = fma2(th2, dot2, dot2);      // (1+tanh)*dot
                    ull t2 = mul2(gn2, u2);              // gn * (1+tanh) * dot
                    xr2[k] = fma2(xn2, t2, xr2[k]);
                    yr2[k] = fma2(yn2, t2, yr2[k]);
                }
            }
        }
    }
}

// -------------------- ETF iterations 1 & 2 (2 channels per block) ------------
__global__ void __launch_bounds__(128) k_iter(int sel) {
    __shared__ ull sXN[HHALO][HW];
    __shared__ ull sYN[HHALO][HW];
    __shared__ ull sGN[HHALO][HW];

    int c0 = blockIdx.z * 2, c1 = c0 + 1;
    const float* xiB = sel ? g_xnB : g_xnA;
    const float* yiB = sel ? g_ynB : g_ynA;
    float* xoB = sel ? g_xnA : g_xnB;
    float* yoB = sel ? g_ynA : g_ynB;

    float ginv0 = 1.0f / __int_as_float(g_gmax[c0]);
    float ginv1 = 1.0f / __int_as_float(g_gmax[c1]);
    int bx0 = blockIdx.x * TW - 2;
    int by0 = blockIdx.y * TH - 2;
    int tid = threadIdx.y * 32 + threadIdx.x;

    load_tile2(sXN, sYN, sGN,
               g_gmag + c0 * NPIX, g_gmag + c1 * NPIX,
               xiB + c0 * NPIX, xiB + c1 * NPIX,
               yiB + c0 * NPIX, yiB + c1 * NPIX,
               ginv0, ginv1, bx0, by0, tid);
    __syncthreads();

    int tx = threadIdx.x;
    int row0 = threadIdx.y * 4;
    int px = blockIdx.x * TW + tx;
    ull xr2[4], yr2[4];
    etf_core2(sXN, sYN, sGN, tx, row0, xr2, yr2);

#pragma unroll
    for (int k = 0; k < 4; k++) {
        float x0, x1, y0v, y1;
        upk(xr2[k], x0, x1);
        upk(yr2[k], y0v, y1);
        float i0 = rsqrtf(fmaf(x0, x0, y0v * y0v));
        float i1 = rsqrtf(fmaf(x1, x1, y1 * y1));
        int o = (blockIdx.y * TH + row0 + k) * WW + px;
        xoB[c0 * NPIX + o] = x0 * i0;
        yoB[c0 * NPIX + o] = y0v * i0;
        xoB[c1 * NPIX + o] = x1 * i1;
        yoB[c1 * NPIX + o] = y1 * i1;
    }
}

// -------------------- ETF iteration 3 fused with angle + stats ---------------
// Per-channel stats: fp32 warp shuffles -> smem block stage -> ONE fp64 atomic
// pair per channel per block.
__global__ void __launch_bounds__(128) k_iter3(float* __restrict__ out) {
    __shared__ ull   sXN[HHALO][HW];
    __shared__ ull   sYN[HHALO][HW];
    __shared__ ull   sGN[HHALO][HW];
    __shared__ float sS[4][4];   // [warp][s0,s20,s1,s21]

    int c0 = blockIdx.z * 2, c1 = c0 + 1;
    float ginv0 = 1.0f / __int_as_float(g_gmax[c0]);
    float ginv1 = 1.0f / __int_as_float(g_gmax[c1]);
    int bx0 = blockIdx.x * TW - 2;
    int by0 = blockIdx.y * TH - 2;
    int tid = threadIdx.y * 32 + threadIdx.x;

    load_tile2(sXN, sYN, sGN,
               g_gmag + c0 * NPIX, g_gmag + c1 * NPIX,
               g_xnA + c0 * NPIX, g_xnA + c1 * NPIX,   // iter3 reads A
               g_ynA + c0 * NPIX, g_ynA + c1 * NPIX,
               ginv0, ginv1, bx0, by0, tid);
    __syncthreads();

    int tx = threadIdx.x;
    int row0 = threadIdx.y * 4;
    int px = blockIdx.x * TW + tx;
    ull xr2[4], yr2[4];
    etf_core2(sXN, sYN, sGN, tx, row0, xr2, yr2);

    float s0 = 0.f, s20 = 0.f, s1 = 0.f, s21 = 0.f;
#pragma unroll
    for (int k = 0; k < 4; k++) {
        float x0, x1, y0v, y1;
        upk(xr2[k], x0, x1);
        upk(yr2[k], y0v, y1);
        int o = (blockIdx.y * TH + row0 + k) * WW + px;
        // normalization cancels inside atan(-y/x); divide directly
        float a0 = atan_fast(__fdividef(-y0v, x0)) * 57.2957795131f;
        float a1 = atan_fast(__fdividef(-y1, x1)) * 57.2957795131f;
        out[c0 * NPIX + o] = a0;
        out[c1 * NPIX + o] = a1;
        s0 += a0; s20 = fmaf(a0, a0, s20);
        s1 += a1; s21 = fmaf(a1, a1, s21);
    }

#pragma unroll
    for (int off = 16; off; off >>= 1) {
        s0  += __shfl_xor_sync(0xffffffffu, s0, off);
        s20 += __shfl_xor_sync(0xffffffffu, s20, off);
        s1  += __shfl_xor_sync(0xffffffffu, s1, off);
        s21 += __shfl_xor_sync(0xffffffffu, s21, off);
    }
    int lane = tid & 31, warp = tid >> 5;
    if (lane == 0) {
        sS[warp][0] = s0; sS[warp][1] = s20;
        sS[warp][2] = s1; sS[warp][3] = s21;
    }
    __syncthreads();
    if (tid == 0) {
        float t0 = sS[0][0] + sS[1][0] + sS[2][0] + sS[3][0];
        float t1 = sS[0][1] + sS[1][1] + sS[2][1] + sS[3][1];
        float t2 = sS[0][2] + sS[1][2] + sS[2][2] + sS[3][2];
        float t3 = sS[0][3] + sS[1][3] + sS[2][3] + sS[3][3];
        atomicAdd(&g_sum[c0], (double)t0);     // return unused -> REDG
        atomicAdd(&g_sumsq[c0], (double)t1);
        atomicAdd(&g_sum[c1], (double)t2);
        atomicAdd(&g_sumsq[c1], (double)t3);
    }
}

// -------------------- normalize (float4) + recycle state --------------------
__global__ void k_norm(float* __restrict__ out) {
    __shared__ float smu, sinv;
    int c = blockIdx.y;
    if (threadIdx.x == 0) {
        double mean = g_sum[c] / (double)NPIX;
        double var  = g_sumsq[c] / (double)NPIX - mean * mean;
        smu  = (float)mean;
        sinv = (float)(1.0 / sqrt(var + 1e-5));
        if (blockIdx.x == 0) g_gmax[c] = 0;   // recycle for next replay
    }
    __syncthreads();
    float4* o4 = (float4*)(out + c * NPIX);
    int i = blockIdx.x * blockDim.x + threadIdx.x;
    float4 v = o4[i];
    float mu = smu, is = sinv;
    v.x = (v.x - mu) * is;
    v.y = (v.y - mu) * is;
    v.z = (v.z - mu) * is;
    v.w = (v.w - mu) * is;
    o4[i] = v;
}

extern "C" void kernel_launch(void* const* d_in, const int* in_sizes, int n_in,
                              void* d_out, int out_size) {
    const float* img = (const float*)d_in[0];
    float* out = (float*)d_out;

    k_sobel<<<dim3(WW / 32, HH / 32, BC), dim3(32, 8)>>>(img);
    k_iter<<<dim3(WW / TW, HH / TH, BC / 2), dim3(32, 4)>>>(0);   // A -> B
    k_iter<<<dim3(WW / TW, HH / TH, BC / 2), dim3(32, 4)>>>(1);   // B -> A
    k_iter3<<<dim3(WW / TW, HH / TH, BC / 2), dim3(32, 4)>>>(out);// A -> out (+stats)
    k_norm<<<dim3(NPIX / 4 / 256, BC), 256>>>(out);
}